// round 11
// baseline (speedup 1.0000x reference)
#include <cuda_runtime.h>
#include <math.h>

#define B 16
#define LQ 2048
#define EMB1 1024
#define EMB2 768
#define HDIM 1024
#define NHEAD 16
#define DH 64
#define GRIDX 18           // grid (18,16) = 288 blocks
#define NBLK (GRIDX * B)   // 288 <= 296 = 148 SMs x 2 -> all co-resident

// Scratch + barrier state (static device globals; no allocation).
__device__ float g_K[B * HDIM];
__device__ float g_V[B * HDIM];
__device__ float g_Weff[B * NHEAD * EMB1];
__device__ float g_c[B * NHEAD];
__device__ unsigned int g_bar = 0;
__device__ unsigned int g_done = 0;

// Packed f32x2 FMA: acc = a*b + acc elementwise on (lo,hi) float pairs.
__device__ __forceinline__ void fma2(unsigned long long& acc,
                                     unsigned long long a, unsigned long long b) {
    asm("fma.rn.f32x2 %0, %1, %2, %0;" : "+l"(acc) : "l"(a), "l"(b));
}
__device__ __forceinline__ float unpack_sum(unsigned long long a) {
    float lo, hi;
    asm("mov.b64 {%0, %1}, %2;" : "=f"(lo), "=f"(hi) : "l"(a));
    return lo + hi;
}

// Grid barrier: all NBLK blocks are co-resident (grid <= min capacity),
// so spinning is deadlock-free. target = NBLK * phase_number.
__device__ __forceinline__ void grid_barrier(unsigned int target, int tid) {
    __syncthreads();
    if (tid == 0) {
        __threadfence();
        atomicAdd(&g_bar, 1u);
        while (atomicAdd(&g_bar, 0u) < target) { }
    }
    __syncthreads();
}

// ---------------------------------------------------------------------------
// Fused persistent kernel: phase A (K/V proj) -> barrier -> phase B (Weff+c
// fold) -> barrier -> phase C (main row-pair loop). 288 blocks, 256 threads.
// ---------------------------------------------------------------------------
__global__ __launch_bounds__(256, 2) void fused_kernel(
        const float* __restrict__ emb1, const float* __restrict__ emb2,
        const float* __restrict__ Wq,   const float* __restrict__ bq,
        const float* __restrict__ Wk,   const float* __restrict__ bk,
        const float* __restrict__ Wv,   const float* __restrict__ bv,
        float* __restrict__ out) {
    extern __shared__ float sm[];
    int tid = threadIdx.x;
    int bid = blockIdx.y * GRIDX + blockIdx.x;   // 0..287

    // ====================== Phase A: K/V projection ======================
    // Blocks 0..255: 4 j-columns each (24 KB staged); warp w does batches
    // {w, w+8}. Identical math to the proven R6 kv_kernel.
    if (bid < 256) {
        float4* wk_s = (float4*)sm;                  // 4*192 float4 = 12 KB
        float4* wv_s = wk_s + 4 * (EMB2 / 4);        // 12 KB
        int j0 = bid * 4;

        const float4* Wk4 = (const float4*)(Wk + j0 * EMB2);
        const float4* Wv4 = (const float4*)(Wv + j0 * EMB2);
        for (int t = tid; t < 4 * (EMB2 / 4); t += 256) wk_s[t] = __ldg(Wk4 + t);
        for (int t = tid; t < 4 * (EMB2 / 4); t += 256) wv_s[t] = __ldg(Wv4 + t);
        __syncthreads();

        int warp = tid >> 5, lane = tid & 31;
#pragma unroll
        for (int bb = 0; bb < 2; bb++) {
            int b = warp + bb * 8;
            const float4* e4 = (const float4*)(emb2 + b * EMB2);
            float4 e[6];
#pragma unroll
            for (int i = 0; i < 6; i++) e[i] = __ldg(&e4[i * 32 + lane]);

            float v[8];                 // v[0..3]=K dots, v[4..7]=V dots
#pragma unroll
            for (int jj = 0; jj < 4; jj++) {
                float ak = 0.f, av = 0.f;
#pragma unroll
                for (int i = 0; i < 6; i++) {
                    float4 k = wk_s[jj * (EMB2 / 4) + i * 32 + lane];
                    float4 w = wv_s[jj * (EMB2 / 4) + i * 32 + lane];
                    ak = fmaf(e[i].x, k.x, ak); ak = fmaf(e[i].y, k.y, ak);
                    ak = fmaf(e[i].z, k.z, ak); ak = fmaf(e[i].w, k.w, ak);
                    av = fmaf(e[i].x, w.x, av); av = fmaf(e[i].y, w.y, av);
                    av = fmaf(e[i].z, w.z, av); av = fmaf(e[i].w, w.w, av);
                }
                v[jj] = ak; v[jj + 4] = av;
            }
#pragma unroll
            for (int s = 0; s < 3; s++) {
                int o = 1 << s;
                int bit = (lane >> s) & 1;
#pragma unroll
                for (int j = 0; j < (4 >> s); j++) {
                    float keep = bit ? v[2 * j + 1] : v[2 * j];
                    float send = bit ? v[2 * j] : v[2 * j + 1];
                    v[j] = keep + __shfl_xor_sync(0xffffffffu, send, o);
                }
            }
            v[0] += __shfl_xor_sync(0xffffffffu, v[0], 8);
            v[0] += __shfl_xor_sync(0xffffffffu, v[0], 16);

            if (lane < 4)
                g_K[b * HDIM + j0 + lane] = v[0] + bk[j0 + lane];
            else if (lane < 8)
                g_V[b * HDIM + j0 + lane - 4] = v[0] + bv[j0 + lane - 4];
        }
    }

    grid_barrier(NBLK, tid);

    // ====================== Phase B: Weff + c fold =======================
    // Blocks 0..255 run TWO 128-thread weff units (u = 2*bid + tid/128).
    // Unit u -> (ec = u&7, h = (u>>3)&15, bg = u>>7); identical math to the
    // proven weff_kernel.
    if (bid < 256) {
        int half = tid >> 7;          // 0 or 1
        int ut = tid & 127;
        float* Wq_s = sm + half * (DH * 128 + 64);
        float* Ks = Wq_s + DH * 128;
        int u = bid * 2 + half;
        int ec = u & 7, h = (u >> 3) & 15, bg = u >> 7;
        int e0 = ec * 128;

        if (ec == 0 && bg == 0 && ut < B) {
            float a = 0.f;
#pragma unroll 16
            for (int d = 0; d < DH; d++)
                a = fmaf(bq[h * DH + d], __ldcg(&g_K[ut * HDIM + h * DH + d]), a);
            g_c[ut * NHEAD + h] = a;
        }

#pragma unroll 8
        for (int d = 0; d < DH; d++)
            Wq_s[d * 128 + ut] = __ldg(&Wq[(h * DH + d) * EMB1 + e0 + ut]);

        for (int bb = 0; bb < 4; bb++) {
            int b = bg * 4 + bb;
            __syncthreads();
            if (ut < DH) Ks[ut] = __ldcg(&g_K[b * HDIM + h * DH + ut]);
            __syncthreads();
            float a = 0.f;
#pragma unroll 16
            for (int d = 0; d < DH; d++)
                a = fmaf(Wq_s[d * 128 + ut], Ks[d], a);
            g_Weff[(b * NHEAD + h) * EMB1 + e0 + ut] = a;
        }
    } else {
        // Keep __syncthreads counts irrelevant: non-participating blocks do
        // no syncs here; barrier below is the only cross-block sync point.
    }

    grid_barrier(2 * NBLK, tid);

    // ====================== Phase C: main row-pair loop ==================
    float* Weff_s = sm;                    // 16384 floats
    float* V_s = sm + NHEAD * EMB1;        // 1024 floats
    float* c_s = V_s + HDIM;               // 16 floats

    int b = blockIdx.y;
    {
        const float4* Wg = (const float4*)(g_Weff + (size_t)b * NHEAD * EMB1);
        float4* Ws4 = (float4*)Weff_s;
#pragma unroll
        for (int i = 0; i < NHEAD * EMB1 / 4 / 256; i++)
            Ws4[i * 256 + tid] = __ldcg(Wg + i * 256 + tid);
        const float4* Vg = (const float4*)(g_V + (size_t)b * HDIM);
        if (tid < HDIM / 4) ((float4*)V_s)[tid] = __ldcg(Vg + tid);
        if (tid < NHEAD) c_s[tid] = __ldcg(&g_c[b * NHEAD + tid]);
    }
    __syncthreads();

    int warp = tid >> 5, lane = tid & 31;
    const ulonglong2* Wsd = (const ulonglong2*)Weff_s;
    const float4* Vs4 = (const float4*)V_s;
    int hi = lane >> 4;
    float c_l = c_s[lane & 15];

    for (int p = blockIdx.x * 8 + warp; p < LQ / 2; p += GRIDX * 8) {
        const ulonglong2* x0p = (const ulonglong2*)(emb1 + ((size_t)b * LQ + 2 * p) * EMB1);
        const ulonglong2* x1p = x0p + EMB1 / 4;

        ulonglong2 x0 = __ldg(x0p + lane);
        ulonglong2 x1 = __ldg(x1p + lane);

        unsigned long long acc0[NHEAD], acc1[NHEAD];
#pragma unroll
        for (int h = 0; h < NHEAD; h++) { acc0[h] = 0ull; acc1[h] = 0ull; }

#pragma unroll
        for (int i = 0; i < 8; i++) {
            ulonglong2 x0n, x1n;
            if (i < 7) {
                x0n = __ldg(x0p + (i + 1) * 32 + lane);
                x1n = __ldg(x1p + (i + 1) * 32 + lane);
            }
#pragma unroll
            for (int h = 0; h < NHEAD; h++) {
                ulonglong2 w = Wsd[h * 256 + i * 32 + lane];
                fma2(acc0[h], x0.x, w.x);
                fma2(acc0[h], x0.y, w.y);
                fma2(acc1[h], x1.x, w.x);
                fma2(acc1[h], x1.y, w.y);
            }
            if (i < 7) { x0 = x0n; x1 = x1n; }
        }

        float v0[NHEAD], v1[NHEAD];
#pragma unroll
        for (int h = 0; h < NHEAD; h++) {
            v0[h] = unpack_sum(acc0[h]);
            v1[h] = unpack_sum(acc1[h]);
        }
#pragma unroll
        for (int s = 0; s < 4; s++) {
            int o = 1 << s;
            int bit = (lane >> s) & 1;
#pragma unroll
            for (int j = 0; j < (8 >> s); j++) {
                float k0 = bit ? v0[2 * j + 1] : v0[2 * j];
                float s0 = bit ? v0[2 * j] : v0[2 * j + 1];
                v0[j] = k0 + __shfl_xor_sync(0xffffffffu, s0, o);
                float k1 = bit ? v1[2 * j + 1] : v1[2 * j];
                float s1 = bit ? v1[2 * j] : v1[2 * j + 1];
                v1[j] = k1 + __shfl_xor_sync(0xffffffffu, s1, o);
            }
        }
        v0[0] += __shfl_xor_sync(0xffffffffu, v0[0], 16);
        v1[0] += __shfl_xor_sync(0xffffffffu, v1[0], 16);

        float sig0 = __fdividef(1.f, 1.f + __expf(-(v0[0] + c_l)));
        float sig1 = __fdividef(1.f, 1.f + __expf(-(v1[0] + c_l)));

        float4* o0 = (float4*)(out + ((size_t)b * LQ + 2 * p) * EMB1);
        float4* o1 = o0 + EMB1 / 4;
#pragma unroll
        for (int i = 0; i < 8; i++) {
            float s0 = __shfl_sync(0xffffffffu, sig0, 2 * i + hi);
            float s1 = __shfl_sync(0xffffffffu, sig1, 2 * i + hi);
            float4 v = Vs4[i * 32 + lane];
            float4 r0, r1;
            r0.x = s0 * v.x; r0.y = s0 * v.y; r0.z = s0 * v.z; r0.w = s0 * v.w;
            r1.x = s1 * v.x; r1.y = s1 * v.y; r1.z = s1 * v.z; r1.w = s1 * v.w;
            o0[i * 32 + lane] = r0;
            o1[i * 32 + lane] = r1;
        }
    }

    // ============ Epilogue: last block resets barrier counters ===========
    __syncthreads();
    if (tid == 0) {
        __threadfence();
        unsigned int d = atomicAdd(&g_done, 1u);
        if (d == NBLK - 1) {              // last arriver: everyone else done
            atomicExch(&g_bar, 0u);
            atomicExch(&g_done, 0u);
        }
    }
}

// ---------------------------------------------------------------------------
extern "C" void kernel_launch(void* const* d_in, const int* in_sizes, int n_in,
                              void* d_out, int out_size) {
    const float* emb1 = (const float*)d_in[0];
    const float* emb2 = (const float*)d_in[1];
    const float* Wq   = (const float*)d_in[2];
    const float* bq   = (const float*)d_in[3];
    const float* Wk   = (const float*)d_in[4];
    const float* bk   = (const float*)d_in[5];
    const float* Wv   = (const float*)d_in[6];
    const float* bv   = (const float*)d_in[7];
    float* out = (float*)d_out;

    int smem = (NHEAD * EMB1 + HDIM + NHEAD) * (int)sizeof(float);  // 69.7 KB
    static bool attr_set = false;
    if (!attr_set) {
        cudaFuncSetAttribute(fused_kernel, cudaFuncAttributeMaxDynamicSharedMemorySize, smem);
        attr_set = true;
    }
    fused_kernel<<<dim3(GRIDX, B), 256, smem>>>(emb1, emb2, Wq, bq, Wk, bk, Wv, bv, out);
}